// round 11
// baseline (speedup 1.0000x reference)
#include <cuda_runtime.h>
#include <cstdint>

// ============================================================================
// ConvLSTMEncoder == 3-layer LSTM (K=3 conv over length-1 dim -> center tap).
//   B=256, T=512, CIN=64, H=128.  gates[b,4H] = [in; h] @ Wc^T + bias
// Round-11: R8's 3-sync macro structure + R10's fat tiles, combined via
// FULL in-lane k-fold (8 chunks, shfl.bfly 4/8/16) -> single pbuf copy per
// layer -> all three GEMVs fit in one sync-free stretch.
//   Macro s (skewed: L0(t=s), L1(t=s-1), L2(t=s-2)):
//     h-assemble -> BAR -> gemv L0+L1+L2 (sync-free) -> BAR -> cells ->
//     split cross-CTA barrier (x(s+1) prefetch overlaps the poll).
//   GEMV: 256 thr; warp = rh(32-row) x rm(16-row) x bh(8-batch);
//         lane = kl(8 k-chunks) x ro(8-row) x bp(4-batch).
//   Lane tile 8 rows x 4 batches: per iter LDS.128(w)x2 + LDS.128(z) +
//   4 DUP2 + 16 FMA2  (3 B/FMA2).  W chunks padded +4 floats so the 8 kl
//   address streams land on disjoint banks per phase.
// 128 CTAs = 16 batch-groups x 8 gate-slices; weights fp32 in SMEM;
// h exchange via L2 __device__ buffer + padded monotonic counter barrier.
// ============================================================================

#define T_STEPS 512

// smem float offsets (chunk strides: L0 24*64+4=1540, L1/2 32*64+4=2052):
#define WOFF_L0 0            // 8*1540 = 12320
#define WOFF_L1 12320        // 8*2052 = 16416
#define WOFF_L2 28736        // 16416
#define ZD_OFF  45152        // z: [448][20] floats = 8960
#define PB_OFF  54112        // pbuf: [3][16][66] floats = 3168
#define SMEM_FLOATS 57280
#define SMEM_BYTES  (SMEM_FLOATS * 4)   // 229120

__device__ float    g_hbuf[3 * 2 * 128 * 256];  // [layer][parity][unit][batch]
__device__ unsigned g_ctr[16 * 32];             // padded: one counter / 128B

__global__ void reset_ctr_kernel() {
    if (threadIdx.x < 16) g_ctr[threadIdx.x * 32] = 0u;
}

__device__ __forceinline__ float fast_rcp(float x) {
    float r; asm("rcp.approx.f32 %0, %1;" : "=f"(r) : "f"(x)); return r;
}
__device__ __forceinline__ float sigm(float x) {
    return fast_rcp(1.0f + __expf(-x));
}
__device__ __forceinline__ float tanh_f(float x) {
    x = fminf(fmaxf(x, -15.0f), 15.0f);
    float e = __expf(-2.0f * x);
    return (1.0f - e) * fast_rcp(1.0f + e);
}

#define FMA2(acc, a, b) asm("fma.rn.f32x2 %0, %1, %2, %0;" : "+l"(acc) : "l"(a), "l"(b))
#define DUP2(d, s)      asm("mov.b64 %0, {%1, %1};" : "=l"(d) : "r"(__float_as_uint(s)))

// butterfly reduce of an f32x2 pair across lanes (xor mask)
__device__ __forceinline__ unsigned long long bfly_add2(unsigned long long a, int m) {
    unsigned lo = (unsigned)a, hi = (unsigned)(a >> 32);
    unsigned plo = __shfl_xor_sync(0xffffffffu, lo, m);
    unsigned phi = __shfl_xor_sync(0xffffffffu, hi, m);
    unsigned long long p = ((unsigned long long)phi << 32) | plo;
    unsigned long long r;
    asm("add.rn.f32x2 %0, %1, %2;" : "=l"(r) : "l"(a), "l"(p));
    return r;
}

// GEMV for one layer: lane tile 8 rows x 4 batches over its k-chunk (KD/8),
// all 8 chunks folded in-lane via bfly 4/8/16; lanes 0..3 store full sums.
template<int KD>
__device__ __forceinline__ void gemv_layer(
    const float* __restrict__ Wbase,   // Wsm + layer offset
    const float* __restrict__ zbase,   // zdf + zrow0*20
    int kc, int r0, int b0, int lane, float* __restrict__ pdst)
{
    constexpr int C  = KD / 8;         // iters per lane
    constexpr int CS = C * 64 + 4;     // padded chunk stride (bank decollide)
    const float* Wcol = Wbase + kc * CS + r0;
    const float* zcol = zbase + kc * (C * 20) + b0;

    unsigned long long acc[4][4];
#pragma unroll
    for (int i = 0; i < 4; i++)
#pragma unroll
        for (int j = 0; j < 4; j++) acc[i][j] = 0ULL;

#pragma unroll 8
    for (int k = 0; k < C; k++) {
        ulonglong2 wa = *(const ulonglong2*)(Wcol + k * 64);      // rows r0..r0+3
        ulonglong2 wb = *(const ulonglong2*)(Wcol + k * 64 + 4);  // rows r0+4..r0+7
        float4 z4 = *(const float4*)(zcol + k * 20);              // batches b0..b0+3
        unsigned long long zz[4];
        DUP2(zz[0], z4.x); DUP2(zz[1], z4.y);
        DUP2(zz[2], z4.z); DUP2(zz[3], z4.w);
#pragma unroll
        for (int j = 0; j < 4; j++) {
            FMA2(acc[0][j], wa.x, zz[j]);
            FMA2(acc[1][j], wa.y, zz[j]);
            FMA2(acc[2][j], wb.x, zz[j]);
            FMA2(acc[3][j], wb.y, zz[j]);
        }
    }
    // fold kl bits (lane bits 2,3,4) -> every lane holds the full-K sum
#pragma unroll
    for (int i = 0; i < 4; i++)
#pragma unroll
        for (int j = 0; j < 4; j++)
            acc[i][j] = bfly_add2(bfly_add2(bfly_add2(acc[i][j], 4), 8), 16);

    if (lane < 4) {   // kc==0 lanes: all (ro,bp) combos present
#pragma unroll
        for (int j = 0; j < 4; j++) {
            float* col = pdst + (b0 + j) * 66 + r0;
#pragma unroll
            for (int i = 0; i < 4; i++)
                *(unsigned long long*)(col + 2 * i) = acc[i][j];
        }
    }
}

__global__ void __launch_bounds__(256, 1) convlstm_kernel(
    const float* __restrict__ x,
    const float* __restrict__ W1, const float* __restrict__ b1,
    const float* __restrict__ W2, const float* __restrict__ b2,
    const float* __restrict__ W3, const float* __restrict__ b3,
    const float* __restrict__ h1i, const float* __restrict__ c1i,
    const float* __restrict__ h2i, const float* __restrict__ c2i,
    const float* __restrict__ h3i, const float* __restrict__ c3i,
    float* __restrict__ out)
{
    extern __shared__ float sm[];
    float* Wsm  = sm;
    float* zdf  = sm + ZD_OFF;
    float* pbuf = sm + PB_OFF;

    const int tid = threadIdx.x;
    const int gid = blockIdx.x & 7;    // gate-slice: hidden units [16*gid, +16)
    const int bg  = blockIdx.x >> 3;   // batch group: batches [16*bg, +16)
    const int bgb = bg << 4;
    unsigned* ctr = &g_ctr[bg * 32];

    // ---- Prologue: weight slices (center tap), [chunk(pad4)][k][row64] ----
    for (int idx = tid; idx < 192 * 64; idx += 256) {
        int k = idx >> 6, r = idx & 63;
        int grow = ((r >> 4) << 7) | (gid << 4) | (r & 15);  // gate*128+gid*16+u
        int c = k / 24, kl = k % 24;
        Wsm[WOFF_L0 + c * 1540 + kl * 64 + r] = W1[(size_t)grow * 576 + k * 3 + 1];
    }
    for (int idx = tid; idx < 256 * 64; idx += 256) {
        int k = idx >> 6, r = idx & 63;
        int grow = ((r >> 4) << 7) | (gid << 4) | (r & 15);
        int c = k >> 5, kl = k & 31;
        Wsm[WOFF_L1 + c * 2052 + kl * 64 + r] = W2[(size_t)grow * 768 + k * 3 + 1];
        Wsm[WOFF_L2 + c * 2052 + kl * 64 + r] = W3[(size_t)grow * 768 + k * 3 + 1];
    }

    // ---- per-thread (u,b) registers: bias + c state ----
    const int u = tid >> 4, b = tid & 15;
    const int gub = (gid << 4) | u;
    float4 bL0 = make_float4(__ldg(&b1[gub]), __ldg(&b1[128 + gub]),
                             __ldg(&b1[256 + gub]), __ldg(&b1[384 + gub]));
    float4 bL1 = make_float4(__ldg(&b2[gub]), __ldg(&b2[128 + gub]),
                             __ldg(&b2[256 + gub]), __ldg(&b2[384 + gub]));
    float4 bL2 = make_float4(__ldg(&b3[gub]), __ldg(&b3[128 + gub]),
                             __ldg(&b3[256 + gub]), __ldg(&b3[384 + gub]));
    const int sidx = (bgb + b) * 128 + gub;
    float c0r = __ldg(&c1i[sidx]);
    float c1r = __ldg(&c2i[sidx]);
    float c2r = __ldg(&c3i[sidx]);

    // ---- publish initial h into both parities ----
    {
        float h0 = __ldg(&h1i[sidx]), h1v = __ldg(&h2i[sidx]), h2v = __ldg(&h3i[sidx]);
        int hb = gub * 256 + bgb + b;
#pragma unroll
        for (int par = 0; par < 2; par++) {
            g_hbuf[(0 * 2 + par) * 32768 + hb] = h0;
            g_hbuf[(1 * 2 + par) * 32768 + hb] = h1v;
            g_hbuf[(2 * 2 + par) * 32768 + hb] = h2v;
        }
    }
    // initial cross-CTA barrier
    unsigned target = 8;
    __syncthreads();
    if (tid == 0) {
        __threadfence();
        atomicAdd(ctr, 1u);
        unsigned v;
        do {
            asm volatile("ld.global.acquire.gpu.u32 %0, [%1];"
                         : "=r"(v) : "l"(ctr) : "memory");
            if (v < target) __nanosleep(20);
        } while (v < target);
    }
    target += 8;
    __syncthreads();

    // ---- initial x(0) assembly ----
    {
        const float* xb = x + (size_t)bgb * (T_STEPS * 64);
        int bb = tid >> 4, k4i = (tid & 15) << 2;
        float4 v = __ldg((const float4*)(xb + (size_t)bb * (T_STEPS * 64) + k4i));
        zdf[(k4i + 0) * 20 + bb] = v.x;
        zdf[(k4i + 1) * 20 + bb] = v.y;
        zdf[(k4i + 2) * 20 + bb] = v.z;
        zdf[(k4i + 3) * 20 + bb] = v.w;
    }

    // GEMV warp/lane geometry: warp = rh x rm x bh; lane = kl x ro x bp
    // Coverage: rows rh(2)xrm(2)xro(2)=8 blocks of 8; batches bh(2)xbp(2)=4
    // blocks of 4; k: kl(8).  8 warps x 32 lanes = complete.
    const int warp = tid >> 5, lane = tid & 31;
    const int rh = warp & 1;
    const int rm = (warp >> 1) & 1;
    const int bh = warp >> 2;
    const int kc = lane >> 2;            // k-chunk (folded in-lane)
    const int ro = (lane >> 1) & 1;
    const int bp = lane & 1;
    const int r0 = rh * 32 + rm * 16 + ro * 8;   // rows r0..r0+7
    const int b0 = bh * 8 + bp * 4;              // batches b0..b0+3

    // ======================= macro-step pipeline =======================
    for (int s = 0; s < T_STEPS + 2; s++) {
        const int pc = s & 1, pp = pc ^ 1;

        // ---- h-assembly: z rows 64..447 (x already written last macro) ----
#pragma unroll
        for (int Lh = 0; Lh < 3; Lh++) {
            const float* src = &g_hbuf[(Lh * 2 + pp) * 32768 + bgb];
#pragma unroll
            for (int i = 0; i < 2; i++) {
                int idx = tid + (i << 8);
                int unit = idx >> 2, b4 = (idx & 3) << 2;
                float4 v = __ldcg((const float4*)&src[unit * 256 + b4]);
                *(float4*)&zdf[(64 + (Lh << 7) + unit) * 20 + b4] = v;
            }
        }
        __syncthreads();

        // ---- all three GEMVs, one sync-free stretch ----
        if (s < T_STEPS)
            gemv_layer<192>(Wsm + WOFF_L0, zdf,            kc, r0, b0, lane, pbuf);
        if (s >= 1 && s <= T_STEPS)
            gemv_layer<256>(Wsm + WOFF_L1, zdf + 64 * 20,  kc, r0, b0, lane, pbuf + 1056);
        if (s >= 2)
            gemv_layer<256>(Wsm + WOFF_L2, zdf + 192 * 20, kc, r0, b0, lane, pbuf + 2112);
        __syncthreads();

        // ---- all three cells (one (u,b) per thread) ----
        if (s < T_STEPS) {
            const float* gb = pbuf + b * 66;
            float gi = gb[u] + bL0.x, gf = gb[16 + u] + bL0.y;
            float go = gb[32 + u] + bL0.z, gg = gb[48 + u] + bL0.w;
            float cn = sigm(gf) * c0r + sigm(gi) * tanh_f(gg);
            float hn = sigm(go) * tanh_f(cn);
            c0r = cn;
            g_hbuf[(0 * 2 + pc) * 32768 + gub * 256 + bgb + b] = hn;
        }
        if (s >= 1 && s <= T_STEPS) {
            const float* gb = pbuf + 1056 + b * 66;
            float gi = gb[u] + bL1.x, gf = gb[16 + u] + bL1.y;
            float go = gb[32 + u] + bL1.z, gg = gb[48 + u] + bL1.w;
            float cn = sigm(gf) * c1r + sigm(gi) * tanh_f(gg);
            float hn = sigm(go) * tanh_f(cn);
            c1r = cn;
            g_hbuf[(1 * 2 + pc) * 32768 + gub * 256 + bgb + b] = hn;
        }
        if (s >= 2) {
            const float* gb = pbuf + 2112 + b * 66;
            float gi = gb[u] + bL2.x, gf = gb[16 + u] + bL2.y;
            float go = gb[32 + u] + bL2.z, gg = gb[48 + u] + bL2.w;
            float cn = sigm(gf) * c2r + sigm(gi) * tanh_f(gg);
            float hn = sigm(go) * tanh_f(cn);
            c2r = cn;
            g_hbuf[(2 * 2 + pc) * 32768 + gub * 256 + bgb + b] = hn;
            if (s == T_STEPS + 1)
                out[(size_t)(bgb + b) * 128 + gub] = hn;
        }

        // ---- split cross-CTA barrier; x(s+1) assembly overlaps the poll ----
        __syncthreads();
        if (tid == 0) {
            __threadfence();
            atomicAdd(ctr, 1u);
        }
        if (s + 1 < T_STEPS) {
            const float* xb = x + (size_t)bgb * (T_STEPS * 64) + (size_t)(s + 1) * 64;
            int bb = tid >> 4, k4i = (tid & 15) << 2;
            float4 v = __ldg((const float4*)(xb + (size_t)bb * (T_STEPS * 64) + k4i));
            zdf[(k4i + 0) * 20 + bb] = v.x;
            zdf[(k4i + 1) * 20 + bb] = v.y;
            zdf[(k4i + 2) * 20 + bb] = v.z;
            zdf[(k4i + 3) * 20 + bb] = v.w;
        }
        if (tid == 0) {
            unsigned v;
            do {
                asm volatile("ld.global.acquire.gpu.u32 %0, [%1];"
                             : "=r"(v) : "l"(ctr) : "memory");
                if (v < target) __nanosleep(20);
            } while (v < target);
        }
        target += 8;
        __syncthreads();
    }
}

extern "C" void kernel_launch(void* const* d_in, const int* in_sizes, int n_in,
                              void* d_out, int out_size) {
    (void)in_sizes; (void)n_in; (void)out_size;
    const float* x  = (const float*)d_in[0];
    const float* W1 = (const float*)d_in[1];
    const float* b1 = (const float*)d_in[2];
    const float* W2 = (const float*)d_in[3];
    const float* b2 = (const float*)d_in[4];
    const float* W3 = (const float*)d_in[5];
    const float* b3 = (const float*)d_in[6];
    const float* h1 = (const float*)d_in[7];
    const float* c1 = (const float*)d_in[8];
    const float* h2 = (const float*)d_in[9];
    const float* c2 = (const float*)d_in[10];
    const float* h3 = (const float*)d_in[11];
    const float* c3 = (const float*)d_in[12];
    float* out = (float*)d_out;

    cudaFuncSetAttribute(convlstm_kernel,
                         cudaFuncAttributeMaxDynamicSharedMemorySize, SMEM_BYTES);
    reset_ctr_kernel<<<1, 32>>>();
    convlstm_kernel<<<128, 256, SMEM_BYTES>>>(x, W1, b1, W2, b2, W3, b3,
                                              h1, c1, h2, c2, h3, c3, out);
}

// round 12
// speedup vs baseline: 1.1588x; 1.1588x over previous
#include <cuda_runtime.h>
#include <cstdint>

// ============================================================================
// ConvLSTMEncoder == 3-layer LSTM (K=3 conv over length-1 dim -> center tap).
//   B=256, T=512, CIN=64, H=128.  gates[b,4H] = [in; h] @ Wc^T + bias
// Round-12: R10 (best, 4422us) with ONE fold level removed.
//   Evidence: R11 added a fold level (+96 shfl/thread) and LOST 0.7ms ->
//   SHFL shares the MIO/crossbar budget with LDS (which is ~60% busy).
//   Change: fold only bfly(16); store 4 pbuf copies (kq warp-bit x in-lane
//   bit3), summed in the cell phase. Net MIO ops/thread ~ -72.
//   pbuf is bank-swizzled stride-64: addr = c*1024 + b*64 + (r ^ 2b)
//   (injective over b per fixed r -> conflict-free cell reads; r,2b both
//   even -> u64 stores aligned).  smem = 45056 + 8960 + 4096 floats
//   = 232448 B = the sm_100 227KB opt-in max, exactly.
// Everything else identical to R10: skewed layer pipeline, per-layer
//   gemv->BAR->cell ladder, split cross-CTA counter barrier with x(s+1)
//   prefetch in the poll window, padded counters, fat 8r x 4b lane tiles.
// ============================================================================

#define T_STEPS 512

// smem float offsets:
#define WOFF_L0 0            // 192*64 = 12288
#define WOFF_L1 12288        // 256*64 = 16384
#define WOFF_L2 28672        // 16384
#define ZD_OFF  45056        // z: [448][20] floats = 8960
#define PB_OFF  54016        // pbuf: [4][16][64] swizzled = 4096
#define SMEM_FLOATS 58112
#define SMEM_BYTES  (SMEM_FLOATS * 4)   // 232448 == 227 KB opt-in max

__device__ float    g_hbuf[3 * 2 * 128 * 256];  // [layer][parity][unit][batch]
__device__ unsigned g_ctr[16 * 32];             // padded: one counter / 128B

__global__ void reset_ctr_kernel() {
    if (threadIdx.x < 16) g_ctr[threadIdx.x * 32] = 0u;
}

__device__ __forceinline__ float fast_rcp(float x) {
    float r; asm("rcp.approx.f32 %0, %1;" : "=f"(r) : "f"(x)); return r;
}
__device__ __forceinline__ float sigm(float x) {
    return fast_rcp(1.0f + __expf(-x));
}
__device__ __forceinline__ float tanh_f(float x) {
    x = fminf(fmaxf(x, -15.0f), 15.0f);
    float e = __expf(-2.0f * x);
    return (1.0f - e) * fast_rcp(1.0f + e);
}

#define FMA2(acc, a, b) asm("fma.rn.f32x2 %0, %1, %2, %0;" : "+l"(acc) : "l"(a), "l"(b))
#define DUP2(d, s)      asm("mov.b64 %0, {%1, %1};" : "=l"(d) : "r"(__float_as_uint(s)))

// butterfly reduce of an f32x2 pair across lane-bit4 (the two 16-lane halves)
__device__ __forceinline__ unsigned long long bfly16_add2(unsigned long long a) {
    unsigned lo = (unsigned)a, hi = (unsigned)(a >> 32);
    unsigned plo = __shfl_xor_sync(0xffffffffu, lo, 16);
    unsigned phi = __shfl_xor_sync(0xffffffffu, hi, 16);
    unsigned long long p = ((unsigned long long)phi << 32) | plo;
    unsigned long long r;
    asm("add.rn.f32x2 %0, %1, %2;" : "=l"(r) : "l"(a), "l"(p));
    return r;
}

// GEMV for one layer: lane tile 8 rows x 4 batches over its k-chunk (KD/8).
// One bfly(16) fold; lanes 0..15 store copy cidx of the swizzled pbuf.
template<int KD>
__device__ __forceinline__ void gemv_layer(
    const float* __restrict__ Wbase,   // Wsm + layer offset
    const float* __restrict__ zbase,   // zdf + zrow0*20
    int kc, int cidx, int r0, int b0, int lane, float* __restrict__ pbuf)
{
    constexpr int C = KD / 8;          // iters per lane
    const float* Wcol = Wbase + kc * (C * 64) + r0;
    const float* zcol = zbase + kc * (C * 20) + b0;

    unsigned long long acc[4][4];
#pragma unroll
    for (int i = 0; i < 4; i++)
#pragma unroll
        for (int j = 0; j < 4; j++) acc[i][j] = 0ULL;

#pragma unroll 4
    for (int k = 0; k < C; k++) {
        ulonglong2 wa = *(const ulonglong2*)(Wcol + k * 64);      // rows r0..r0+3
        ulonglong2 wb = *(const ulonglong2*)(Wcol + k * 64 + 4);  // rows r0+4..r0+7
        float4 z4 = *(const float4*)(zcol + k * 20);              // batches b0..b0+3
        unsigned long long zz[4];
        DUP2(zz[0], z4.x); DUP2(zz[1], z4.y);
        DUP2(zz[2], z4.z); DUP2(zz[3], z4.w);
#pragma unroll
        for (int j = 0; j < 4; j++) {
            FMA2(acc[0][j], wa.x, zz[j]);
            FMA2(acc[1][j], wa.y, zz[j]);
            FMA2(acc[2][j], wb.x, zz[j]);
            FMA2(acc[3][j], wb.y, zz[j]);
        }
    }
    // fold lane-bit4 only (chunks kc and kc^2 pair up)
#pragma unroll
    for (int i = 0; i < 4; i++)
#pragma unroll
        for (int j = 0; j < 4; j++)
            acc[i][j] = bfly16_add2(acc[i][j]);

    if (lane < 16) {   // bit4==0 lanes hold the folded pair for copy cidx
        float* pd = pbuf + cidx * 1024;
#pragma unroll
        for (int j = 0; j < 4; j++) {
            const int b = b0 + j;
            float* col = pd + b * 64;
            const int sw = 2 * b;
#pragma unroll
            for (int i = 0; i < 4; i++)
                *(unsigned long long*)(col + ((r0 + 2 * i) ^ sw)) = acc[i][j];
        }
    }
}

__global__ void __launch_bounds__(256, 1) convlstm_kernel(
    const float* __restrict__ x,
    const float* __restrict__ W1, const float* __restrict__ b1,
    const float* __restrict__ W2, const float* __restrict__ b2,
    const float* __restrict__ W3, const float* __restrict__ b3,
    const float* __restrict__ h1i, const float* __restrict__ c1i,
    const float* __restrict__ h2i, const float* __restrict__ c2i,
    const float* __restrict__ h3i, const float* __restrict__ c3i,
    float* __restrict__ out)
{
    extern __shared__ float sm[];
    float* Wsm  = sm;
    float* zdf  = sm + ZD_OFF;
    float* pbuf = sm + PB_OFF;

    const int tid = threadIdx.x;
    const int gid = blockIdx.x & 7;    // gate-slice: hidden units [16*gid, +16)
    const int bg  = blockIdx.x >> 3;   // batch group: batches [16*bg, +16)
    const int bgb = bg << 4;
    unsigned* ctr = &g_ctr[bg * 32];

    // ---- Prologue: weight slices (center tap), plain [k][row64] ----
    for (int idx = tid; idx < 192 * 64; idx += 256) {
        int k = idx >> 6, r = idx & 63;
        int grow = ((r >> 4) << 7) | (gid << 4) | (r & 15);  // gate*128+gid*16+u
        Wsm[WOFF_L0 + idx] = W1[(size_t)grow * 576 + k * 3 + 1];
    }
    for (int idx = tid; idx < 256 * 64; idx += 256) {
        int k = idx >> 6, r = idx & 63;
        int grow = ((r >> 4) << 7) | (gid << 4) | (r & 15);
        Wsm[WOFF_L1 + idx] = W2[(size_t)grow * 768 + k * 3 + 1];
        Wsm[WOFF_L2 + idx] = W3[(size_t)grow * 768 + k * 3 + 1];
    }

    // ---- per-thread (u,b) registers: bias + c state ----
    const int u = tid >> 4, b = tid & 15;
    const int gub = (gid << 4) | u;
    float4 bL0 = make_float4(__ldg(&b1[gub]), __ldg(&b1[128 + gub]),
                             __ldg(&b1[256 + gub]), __ldg(&b1[384 + gub]));
    float4 bL1 = make_float4(__ldg(&b2[gub]), __ldg(&b2[128 + gub]),
                             __ldg(&b2[256 + gub]), __ldg(&b2[384 + gub]));
    float4 bL2 = make_float4(__ldg(&b3[gub]), __ldg(&b3[128 + gub]),
                             __ldg(&b3[256 + gub]), __ldg(&b3[384 + gub]));
    const int sidx = (bgb + b) * 128 + gub;
    float c0r = __ldg(&c1i[sidx]);
    float c1r = __ldg(&c2i[sidx]);
    float c2r = __ldg(&c3i[sidx]);

    // ---- publish initial h into both parities ----
    {
        float h0 = __ldg(&h1i[sidx]), h1v = __ldg(&h2i[sidx]), h2v = __ldg(&h3i[sidx]);
        int hb = gub * 256 + bgb + b;
#pragma unroll
        for (int par = 0; par < 2; par++) {
            g_hbuf[(0 * 2 + par) * 32768 + hb] = h0;
            g_hbuf[(1 * 2 + par) * 32768 + hb] = h1v;
            g_hbuf[(2 * 2 + par) * 32768 + hb] = h2v;
        }
    }
    // initial cross-CTA barrier
    unsigned target = 8;
    __syncthreads();
    if (tid == 0) {
        __threadfence();
        atomicAdd(ctr, 1u);
        unsigned v;
        do {
            asm volatile("ld.global.acquire.gpu.u32 %0, [%1];"
                         : "=r"(v) : "l"(ctr) : "memory");
            if (v < target) __nanosleep(20);
        } while (v < target);
    }
    target += 8;
    __syncthreads();

    // ---- initial x(0) assembly ----
    {
        const float* xb = x + (size_t)bgb * (T_STEPS * 64);
        int bb = tid >> 4, k4i = (tid & 15) << 2;
        float4 v = __ldg((const float4*)(xb + (size_t)bb * (T_STEPS * 64) + k4i));
        zdf[(k4i + 0) * 20 + bb] = v.x;
        zdf[(k4i + 1) * 20 + bb] = v.y;
        zdf[(k4i + 2) * 20 + bb] = v.z;
        zdf[(k4i + 3) * 20 + bb] = v.w;
    }

    // GEMV warp/lane geometry (identical to R10)
    const int warp = tid >> 5, lane = tid & 31;
    const int kq = warp & 1;             // k-half (warp-level)
    const int rh = (warp >> 1) & 1;      // 32-row half
    const int bh = warp >> 2;            // 8-batch half
    const int ro = lane & 3;             // 8-row block within half
    const int bp = (lane >> 2) & 1;      // 4-batch within half
    const int kl = lane >> 3;            // in-lane k-chunk bits (bit4 folded)
    const int kc = kq * 4 + kl;          // k-chunk 0..7 for addressing
    const int cidx = kq * 2 + (kl & 1);  // pbuf copy for storing lanes (<16)
    const int r0 = rh * 32 + ro * 8;     // rows r0..r0+7
    const int b0 = bh * 8 + bp * 4;      // batches b0..b0+3

    // ======================= macro-step pipeline =======================
    for (int s = 0; s < T_STEPS + 2; s++) {
        const int pc = s & 1, pp = pc ^ 1;

        // ---- h-assembly: z rows 64..447 (x already written last macro) ----
#pragma unroll
        for (int Lh = 0; Lh < 3; Lh++) {
            const float* src = &g_hbuf[(Lh * 2 + pp) * 32768 + bgb];
#pragma unroll
            for (int i = 0; i < 2; i++) {
                int idx = tid + (i << 8);
                int unit = idx >> 2, b4 = (idx & 3) << 2;
                float4 v = __ldcg((const float4*)&src[unit * 256 + b4]);
                *(float4*)&zdf[(64 + (Lh << 7) + unit) * 20 + b4] = v;
            }
        }
        __syncthreads();

        // -------- L0: t = s  (z rows 0..191) --------
        if (s < T_STEPS)
            gemv_layer<192>(Wsm + WOFF_L0, zdf, kc, cidx, r0, b0, lane, pbuf);
        __syncthreads();
        if (s < T_STEPS) {
            const int sw = 2 * b;
            float gi = bL0.x, gf = bL0.y, go = bL0.z, gg = bL0.w;
#pragma unroll
            for (int c = 0; c < 4; c++) {
                const float* gb = pbuf + c * 1024 + b * 64;
                gi += gb[u ^ sw];
                gf += gb[(16 + u) ^ sw];
                go += gb[(32 + u) ^ sw];
                gg += gb[(48 + u) ^ sw];
            }
            float cn = sigm(gf) * c0r + sigm(gi) * tanh_f(gg);
            float hn = sigm(go) * tanh_f(cn);
            c0r = cn;
            g_hbuf[(0 * 2 + pc) * 32768 + gub * 256 + bgb + b] = hn;
        }
        __syncthreads();

        // -------- L1: t = s-1  (z rows 64..319) --------
        if (s >= 1 && s <= T_STEPS)
            gemv_layer<256>(Wsm + WOFF_L1, zdf + 64 * 20, kc, cidx, r0, b0, lane, pbuf);
        __syncthreads();
        if (s >= 1 && s <= T_STEPS) {
            const int sw = 2 * b;
            float gi = bL1.x, gf = bL1.y, go = bL1.z, gg = bL1.w;
#pragma unroll
            for (int c = 0; c < 4; c++) {
                const float* gb = pbuf + c * 1024 + b * 64;
                gi += gb[u ^ sw];
                gf += gb[(16 + u) ^ sw];
                go += gb[(32 + u) ^ sw];
                gg += gb[(48 + u) ^ sw];
            }
            float cn = sigm(gf) * c1r + sigm(gi) * tanh_f(gg);
            float hn = sigm(go) * tanh_f(cn);
            c1r = cn;
            g_hbuf[(1 * 2 + pc) * 32768 + gub * 256 + bgb + b] = hn;
        }
        __syncthreads();

        // -------- L2: t = s-2  (z rows 192..447) --------
        if (s >= 2)
            gemv_layer<256>(Wsm + WOFF_L2, zdf + 192 * 20, kc, cidx, r0, b0, lane, pbuf);
        __syncthreads();
        if (s >= 2) {
            const int sw = 2 * b;
            float gi = bL2.x, gf = bL2.y, go = bL2.z, gg = bL2.w;
#pragma unroll
            for (int c = 0; c < 4; c++) {
                const float* gb = pbuf + c * 1024 + b * 64;
                gi += gb[u ^ sw];
                gf += gb[(16 + u) ^ sw];
                go += gb[(32 + u) ^ sw];
                gg += gb[(48 + u) ^ sw];
            }
            float cn = sigm(gf) * c2r + sigm(gi) * tanh_f(gg);
            float hn = sigm(go) * tanh_f(cn);
            c2r = cn;
            g_hbuf[(2 * 2 + pc) * 32768 + gub * 256 + bgb + b] = hn;
            if (s == T_STEPS + 1)
                out[(size_t)(bgb + b) * 128 + gub] = hn;
        }

        // ---- split cross-CTA barrier; x(s+1) assembly overlaps the poll ----
        __syncthreads();
        if (tid == 0) {
            __threadfence();
            atomicAdd(ctr, 1u);
        }
        if (s + 1 < T_STEPS) {
            const float* xb = x + (size_t)bgb * (T_STEPS * 64) + (size_t)(s + 1) * 64;
            int bb = tid >> 4, k4i = (tid & 15) << 2;
            float4 v = __ldg((const float4*)(xb + (size_t)bb * (T_STEPS * 64) + k4i));
            zdf[(k4i + 0) * 20 + bb] = v.x;
            zdf[(k4i + 1) * 20 + bb] = v.y;
            zdf[(k4i + 2) * 20 + bb] = v.z;
            zdf[(k4i + 3) * 20 + bb] = v.w;
        }
        if (tid == 0) {
            unsigned v;
            do {
                asm volatile("ld.global.acquire.gpu.u32 %0, [%1];"
                             : "=r"(v) : "l"(ctr) : "memory");
                if (v < target) __nanosleep(20);
            } while (v < target);
        }
        target += 8;
        __syncthreads();
    }
}

extern "C" void kernel_launch(void* const* d_in, const int* in_sizes, int n_in,
                              void* d_out, int out_size) {
    (void)in_sizes; (void)n_in; (void)out_size;
    const float* x  = (const float*)d_in[0];
    const float* W1 = (const float*)d_in[1];
    const float* b1 = (const float*)d_in[2];
    const float* W2 = (const float*)d_in[3];
    const float* b2 = (const float*)d_in[4];
    const float* W3 = (const float*)d_in[5];
    const float* b3 = (const float*)d_in[6];
    const float* h1 = (const float*)d_in[7];
    const float* c1 = (const float*)d_in[8];
    const float* h2 = (const float*)d_in[9];
    const float* c2 = (const float*)d_in[10];
    const float* h3 = (const float*)d_in[11];
    const float* c3 = (const float*)d_in[12];
    float* out = (float*)d_out;

    cudaFuncSetAttribute(convlstm_kernel,
                         cudaFuncAttributeMaxDynamicSharedMemorySize, SMEM_BYTES);
    reset_ctr_kernel<<<1, 32>>>();
    convlstm_kernel<<<128, 256, SMEM_BYTES>>>(x, W1, b1, W2, b2, W3, b3,
                                              h1, c1, h2, c2, h3, c3, out);
}

// round 13
// speedup vs baseline: 1.1966x; 1.0326x over previous
#include <cuda_runtime.h>
#include <cstdint>

// ============================================================================
// ConvLSTMEncoder == 3-layer LSTM (K=3 conv over length-1 dim -> center tap).
//   B=256, T=512, CIN=64, H=128.  gates[b,4H] = [in; h] @ Wc^T + bias
// Round-13: overlap ladder. Same work as R10/R12 (best, 4422us), rescheduled
// so cells, h-assembly latency, and BARs hide under the GEMV phases:
//   phase A: asm h0 (z rows 64..191)                       -> BAR
//   phase B: issue h1/h2 LDGs; gemv L0 -> set0; STS h1/h2  -> BAR
//   phase C: gemv L1 -> set1; cell L0 (reads set0)         -> BAR
//   phase D: gemv L2 -> set0; cell L1 (reads set1)         -> BAR
//   phase E: cell L2 (reads set0); publish; group barrier (x(s+1) prefetch
//            overlaps the poll window)
// 6 sync points vs 9; no new shfl (R11 lesson), no new LDS work.
// GEMV: R10 geometry. warp = kq x rh x bh; lane = ro x bp x kl; lane tile
//   8 rows x 4 batches; fold bfly(8)+bfly(16) -> lanes 0..7 store copy kq
//   of pbuf set (0/1), bank-swizzled stride-64 (R12 layout, conflict-free).
// 128 CTAs = 16 batch-groups x 8 gate-slices; weights fp32 in SMEM;
// h exchange via L2 __device__ buffer + padded monotonic counter barrier.
// ============================================================================

#define T_STEPS 512

// smem float offsets:
#define WOFF_L0 0            // 192*64 = 12288
#define WOFF_L1 12288        // 256*64 = 16384
#define WOFF_L2 28672        // 16384
#define ZD_OFF  45056        // z: [448][20] floats = 8960
#define PB_OFF  54016        // pbuf: [2 sets][2 copies][16][64] = 4096
#define SMEM_FLOATS 58112
#define SMEM_BYTES  (SMEM_FLOATS * 4)   // 232448 (opt-in max, proven R12)

__device__ float    g_hbuf[3 * 2 * 128 * 256];  // [layer][parity][unit][batch]
__device__ unsigned g_ctr[16 * 32];             // padded: one counter / 128B

__global__ void reset_ctr_kernel() {
    if (threadIdx.x < 16) g_ctr[threadIdx.x * 32] = 0u;
}

__device__ __forceinline__ float fast_rcp(float x) {
    float r; asm("rcp.approx.f32 %0, %1;" : "=f"(r) : "f"(x)); return r;
}
__device__ __forceinline__ float sigm(float x) {
    return fast_rcp(1.0f + __expf(-x));
}
__device__ __forceinline__ float tanh_f(float x) {
    x = fminf(fmaxf(x, -15.0f), 15.0f);
    float e = __expf(-2.0f * x);
    return (1.0f - e) * fast_rcp(1.0f + e);
}

#define FMA2(acc, a, b) asm("fma.rn.f32x2 %0, %1, %2, %0;" : "+l"(acc) : "l"(a), "l"(b))
#define DUP2(d, s)      asm("mov.b64 %0, {%1, %1};" : "=l"(d) : "r"(__float_as_uint(s)))

// butterfly reduce of an f32x2 pair across lanes (xor mask)
__device__ __forceinline__ unsigned long long bfly_add2(unsigned long long a, int m) {
    unsigned lo = (unsigned)a, hi = (unsigned)(a >> 32);
    unsigned plo = __shfl_xor_sync(0xffffffffu, lo, m);
    unsigned phi = __shfl_xor_sync(0xffffffffu, hi, m);
    unsigned long long p = ((unsigned long long)phi << 32) | plo;
    unsigned long long r;
    asm("add.rn.f32x2 %0, %1, %2;" : "=l"(r) : "l"(a), "l"(p));
    return r;
}

// GEMV for one layer: lane tile 8 rows x 4 batches over its k-chunk (KD/8).
// Folds lane bits 3,4 (bfly 8,16); lanes 0..7 store copy kq into pset.
template<int KD>
__device__ __forceinline__ void gemv_layer(
    const float* __restrict__ Wbase,   // Wsm + layer offset
    const float* __restrict__ zbase,   // zdf + zrow0*20
    int kc, int kq, int r0, int b0, int lane, float* __restrict__ pset)
{
    constexpr int C = KD / 8;          // iters per lane
    const float* Wcol = Wbase + kc * (C * 64) + r0;
    const float* zcol = zbase + kc * (C * 20) + b0;

    unsigned long long acc[4][4];
#pragma unroll
    for (int i = 0; i < 4; i++)
#pragma unroll
        for (int j = 0; j < 4; j++) acc[i][j] = 0ULL;

#pragma unroll 4
    for (int k = 0; k < C; k++) {
        ulonglong2 wa = *(const ulonglong2*)(Wcol + k * 64);      // rows r0..r0+3
        ulonglong2 wb = *(const ulonglong2*)(Wcol + k * 64 + 4);  // rows r0+4..r0+7
        float4 z4 = *(const float4*)(zcol + k * 20);              // batches b0..b0+3
        unsigned long long zz[4];
        DUP2(zz[0], z4.x); DUP2(zz[1], z4.y);
        DUP2(zz[2], z4.z); DUP2(zz[3], z4.w);
#pragma unroll
        for (int j = 0; j < 4; j++) {
            FMA2(acc[0][j], wa.x, zz[j]);
            FMA2(acc[1][j], wa.y, zz[j]);
            FMA2(acc[2][j], wb.x, zz[j]);
            FMA2(acc[3][j], wb.y, zz[j]);
        }
    }
    // fold lane bits 3,4 -> lanes 0..7 hold this warp's kq-half sums
#pragma unroll
    for (int i = 0; i < 4; i++)
#pragma unroll
        for (int j = 0; j < 4; j++)
            acc[i][j] = bfly_add2(bfly_add2(acc[i][j], 8), 16);

    if (lane < 8) {
        float* pd = pset + kq * 1024;
#pragma unroll
        for (int j = 0; j < 4; j++) {
            const int b = b0 + j;
            float* col = pd + b * 64;
            const int sw = 2 * b;
#pragma unroll
            for (int i = 0; i < 4; i++)
                *(unsigned long long*)(col + ((r0 + 2 * i) ^ sw)) = acc[i][j];
        }
    }
}

// cell phase helper: gate sums from a pbuf set (2 copies), swizzled reads
__device__ __forceinline__ float4 gate_sums(const float* __restrict__ pset,
                                            int u, int b, float4 bL)
{
    const int sw = 2 * b;
    float gi = bL.x, gf = bL.y, go = bL.z, gg = bL.w;
#pragma unroll
    for (int c = 0; c < 2; c++) {
        const float* gb = pset + c * 1024 + b * 64;
        gi += gb[u ^ sw];
        gf += gb[(16 + u) ^ sw];
        go += gb[(32 + u) ^ sw];
        gg += gb[(48 + u) ^ sw];
    }
    return make_float4(gi, gf, go, gg);
}

__global__ void __launch_bounds__(256, 1) convlstm_kernel(
    const float* __restrict__ x,
    const float* __restrict__ W1, const float* __restrict__ b1,
    const float* __restrict__ W2, const float* __restrict__ b2,
    const float* __restrict__ W3, const float* __restrict__ b3,
    const float* __restrict__ h1i, const float* __restrict__ c1i,
    const float* __restrict__ h2i, const float* __restrict__ c2i,
    const float* __restrict__ h3i, const float* __restrict__ c3i,
    float* __restrict__ out)
{
    extern __shared__ float sm[];
    float* Wsm  = sm;
    float* zdf  = sm + ZD_OFF;
    float* pbuf = sm + PB_OFF;

    const int tid = threadIdx.x;
    const int gid = blockIdx.x & 7;    // gate-slice: hidden units [16*gid, +16)
    const int bg  = blockIdx.x >> 3;   // batch group: batches [16*bg, +16)
    const int bgb = bg << 4;
    unsigned* ctr = &g_ctr[bg * 32];

    // ---- Prologue: weight slices (center tap), plain [k][row64] ----
    for (int idx = tid; idx < 192 * 64; idx += 256) {
        int k = idx >> 6, r = idx & 63;
        int grow = ((r >> 4) << 7) | (gid << 4) | (r & 15);  // gate*128+gid*16+u
        Wsm[WOFF_L0 + idx] = W1[(size_t)grow * 576 + k * 3 + 1];
    }
    for (int idx = tid; idx < 256 * 64; idx += 256) {
        int k = idx >> 6, r = idx & 63;
        int grow = ((r >> 4) << 7) | (gid << 4) | (r & 15);
        Wsm[WOFF_L1 + idx] = W2[(size_t)grow * 768 + k * 3 + 1];
        Wsm[WOFF_L2 + idx] = W3[(size_t)grow * 768 + k * 3 + 1];
    }

    // ---- per-thread (u,b) registers: bias + c state ----
    const int u = tid >> 4, b = tid & 15;
    const int gub = (gid << 4) | u;
    float4 bL0 = make_float4(__ldg(&b1[gub]), __ldg(&b1[128 + gub]),
                             __ldg(&b1[256 + gub]), __ldg(&b1[384 + gub]));
    float4 bL1 = make_float4(__ldg(&b2[gub]), __ldg(&b2[128 + gub]),
                             __ldg(&b2[256 + gub]), __ldg(&b2[384 + gub]));
    float4 bL2 = make_float4(__ldg(&b3[gub]), __ldg(&b3[128 + gub]),
                             __ldg(&b3[256 + gub]), __ldg(&b3[384 + gub]));
    const int sidx = (bgb + b) * 128 + gub;
    float c0r = __ldg(&c1i[sidx]);
    float c1r = __ldg(&c2i[sidx]);
    float c2r = __ldg(&c3i[sidx]);

    // ---- publish initial h into both parities ----
    {
        float h0 = __ldg(&h1i[sidx]), h1v = __ldg(&h2i[sidx]), h2v = __ldg(&h3i[sidx]);
        int hb = gub * 256 + bgb + b;
#pragma unroll
        for (int par = 0; par < 2; par++) {
            g_hbuf[(0 * 2 + par) * 32768 + hb] = h0;
            g_hbuf[(1 * 2 + par) * 32768 + hb] = h1v;
            g_hbuf[(2 * 2 + par) * 32768 + hb] = h2v;
        }
    }
    // initial cross-CTA barrier
    unsigned target = 8;
    __syncthreads();
    if (tid == 0) {
        __threadfence();
        atomicAdd(ctr, 1u);
        unsigned v;
        do {
            asm volatile("ld.global.acquire.gpu.u32 %0, [%1];"
                         : "=r"(v) : "l"(ctr) : "memory");
            if (v < target) __nanosleep(20);
        } while (v < target);
    }
    target += 8;
    __syncthreads();

    // ---- initial x(0) assembly ----
    {
        const float* xb = x + (size_t)bgb * (T_STEPS * 64);
        int bb = tid >> 4, k4i = (tid & 15) << 2;
        float4 v = __ldg((const float4*)(xb + (size_t)bb * (T_STEPS * 64) + k4i));
        zdf[(k4i + 0) * 20 + bb] = v.x;
        zdf[(k4i + 1) * 20 + bb] = v.y;
        zdf[(k4i + 2) * 20 + bb] = v.z;
        zdf[(k4i + 3) * 20 + bb] = v.w;
    }

    // GEMV warp/lane geometry (R10)
    const int warp = tid >> 5, lane = tid & 31;
    const int kq = warp & 1;             // k-half (pbuf copy)
    const int rh = (warp >> 1) & 1;      // 32-row half
    const int bh = warp >> 2;            // 8-batch half
    const int ro = lane & 3;             // 8-row block within half
    const int bp = (lane >> 2) & 1;      // 4-batch within half
    const int kl = lane >> 3;            // in-lane k-chunk bits (folded)
    const int kc = kq * 4 + kl;          // k-chunk 0..7
    const int r0 = rh * 32 + ro * 8;     // rows r0..r0+7
    const int b0 = bh * 8 + bp * 4;      // batches b0..b0+3

    // h-assembly thread indexing
    const int aunit = tid >> 2;                // 0..63 (x2 with +256)
    const int ab4   = (tid & 3) << 2;

    // ======================= macro-step pipeline =======================
    for (int s = 0; s < T_STEPS + 2; s++) {
        const int pc = s & 1, pp = pc ^ 1;

        // ---- phase A: asm h0 (z rows 64..191) ----
        if (s <= T_STEPS) {
            const float* src = &g_hbuf[(0 * 2 + pp) * 32768 + bgb];
#pragma unroll
            for (int i = 0; i < 2; i++) {
                int unit = aunit + (i << 6);
                float4 v = __ldcg((const float4*)&src[unit * 256 + ab4]);
                *(float4*)&zdf[(64 + unit) * 20 + ab4] = v;
            }
        }
        __syncthreads();

        // ---- phase B: issue h1/h2 loads; gemv L0 -> set0; store h1/h2 ----
        float4 hv[4];
#pragma unroll
        for (int Lh = 1; Lh <= 2; Lh++) {
            const float* src = &g_hbuf[(Lh * 2 + pp) * 32768 + bgb];
#pragma unroll
            for (int i = 0; i < 2; i++) {
                int unit = aunit + (i << 6);
                hv[(Lh - 1) * 2 + i] = __ldcg((const float4*)&src[unit * 256 + ab4]);
            }
        }
        if (s < T_STEPS)
            gemv_layer<192>(Wsm + WOFF_L0, zdf, kc, kq, r0, b0, lane, pbuf);
#pragma unroll
        for (int Lh = 1; Lh <= 2; Lh++) {
#pragma unroll
            for (int i = 0; i < 2; i++) {
                int unit = aunit + (i << 6);
                *(float4*)&zdf[(64 + (Lh << 7) + unit) * 20 + ab4] = hv[(Lh - 1) * 2 + i];
            }
        }
        __syncthreads();

        // ---- phase C: gemv L1 -> set1; cell L0 (reads set0) ----
        if (s >= 1 && s <= T_STEPS)
            gemv_layer<256>(Wsm + WOFF_L1, zdf + 64 * 20, kc, kq, r0, b0, lane,
                            pbuf + 2048);
        if (s < T_STEPS) {
            float4 g = gate_sums(pbuf, u, b, bL0);
            float cn = sigm(g.y) * c0r + sigm(g.x) * tanh_f(g.w);
            float hn = sigm(g.z) * tanh_f(cn);
            c0r = cn;
            g_hbuf[(0 * 2 + pc) * 32768 + gub * 256 + bgb + b] = hn;
        }
        __syncthreads();

        // ---- phase D: gemv L2 -> set0; cell L1 (reads set1) ----
        if (s >= 2)
            gemv_layer<256>(Wsm + WOFF_L2, zdf + 192 * 20, kc, kq, r0, b0, lane,
                            pbuf);
        if (s >= 1 && s <= T_STEPS) {
            float4 g = gate_sums(pbuf + 2048, u, b, bL1);
            float cn = sigm(g.y) * c1r + sigm(g.x) * tanh_f(g.w);
            float hn = sigm(g.z) * tanh_f(cn);
            c1r = cn;
            g_hbuf[(1 * 2 + pc) * 32768 + gub * 256 + bgb + b] = hn;
        }
        __syncthreads();

        // ---- phase E: cell L2 (reads set0) ----
        if (s >= 2) {
            float4 g = gate_sums(pbuf, u, b, bL2);
            float cn = sigm(g.y) * c2r + sigm(g.x) * tanh_f(g.w);
            float hn = sigm(g.z) * tanh_f(cn);
            c2r = cn;
            g_hbuf[(2 * 2 + pc) * 32768 + gub * 256 + bgb + b] = hn;
            if (s == T_STEPS + 1)
                out[(size_t)(bgb + b) * 128 + gub] = hn;
        }

        // ---- split cross-CTA barrier; x(s+1) assembly overlaps the poll ----
        __syncthreads();
        if (tid == 0) {
            __threadfence();
            atomicAdd(ctr, 1u);
        }
        if (s + 1 < T_STEPS) {
            const float* xb = x + (size_t)bgb * (T_STEPS * 64) + (size_t)(s + 1) * 64;
            int bb = tid >> 4, k4i = (tid & 15) << 2;
            float4 v = __ldg((const float4*)(xb + (size_t)bb * (T_STEPS * 64) + k4i));
            zdf[(k4i + 0) * 20 + bb] = v.x;
            zdf[(k4i + 1) * 20 + bb] = v.y;
            zdf[(k4i + 2) * 20 + bb] = v.z;
            zdf[(k4i + 3) * 20 + bb] = v.w;
        }
        if (tid == 0) {
            unsigned v;
            do {
                asm volatile("ld.global.acquire.gpu.u32 %0, [%1];"
                             : "=r"(v) : "l"(ctr) : "memory");
                if (v < target) __nanosleep(20);
            } while (v < target);
        }
        target += 8;
        __syncthreads();
    }
}

extern "C" void kernel_launch(void* const* d_in, const int* in_sizes, int n_in,
                              void* d_out, int out_size) {
    (void)in_sizes; (void)n_in; (void)out_size;
    const float* x  = (const float*)d_in[0];
    const float* W1 = (const float*)d_in[1];
    const float* b1 = (const float*)d_in[2];
    const float* W2 = (const float*)d_in[3];
    const float* b2 = (const float*)d_in[4];
    const float* W3 = (const float*)d_in[5];
    const float* b3 = (const float*)d_in[6];
    const float* h1 = (const float*)d_in[7];
    const float* c1 = (const float*)d_in[8];
    const float* h2 = (const float*)d_in[9];
    const float* c2 = (const float*)d_in[10];
    const float* h3 = (const float*)d_in[11];
    const float* c3 = (const float*)d_in[12];
    float* out = (float*)d_out;

    cudaFuncSetAttribute(convlstm_kernel,
                         cudaFuncAttributeMaxDynamicSharedMemorySize, SMEM_BYTES);
    reset_ctr_kernel<<<1, 32>>>();
    convlstm_kernel<<<128, 256, SMEM_BYTES>>>(x, W1, b1, W2, b2, W3, b3,
                                              h1, c1, h2, c2, h3, c3, out);
}